// round 16
// baseline (speedup 1.0000x reference)
#include <cuda_runtime.h>
#include <cuda_fp16.h>
#include <cstdint>

#define N_NODES 50000
#define N_EDGES 600000
#define IN_DIM  128
#define HID     256

#define SCAN_B  1024
#define NBLK    ((N_NODES + SCAN_B - 1) / SCAN_B)   // 49

// ---------------- device scratch (no allocation allowed) ----------------
__device__ int    g_count[N_NODES];
__device__ int    g_fill[N_NODES];
__device__ int    g_rowptr[N_NODES + 1];
__device__ int    g_bsum[NBLK];
__device__ int    g_boff[NBLK];
__device__ int    g_ticket;          // zero-initialized; reset after each use
__device__ float  g_dinv[N_NODES];
__device__ int    g_col[N_EDGES];
__device__ __half g_x16[(size_t)N_NODES * IN_DIM];     // x in fp16
__device__ __half g_w1t[256 * 128];                    // W1^T fp16 [n][k]
__device__ __half g_w2t[256 * 256];                    // W2^T fp16 [n][k]
__device__ __half g_xagg16[(size_t)N_NODES * IN_DIM];  // agg1 out fp16
__device__ __half g_h1h[(size_t)N_NODES * HID];        // h1 fp16
__device__ __half g_h1agg16[(size_t)N_NODES * HID];    // agg2 out fp16

// ---------------- preprocessing ----------------
__global__ void k_init(const float* __restrict__ x, const float* __restrict__ W1,
                       const float* __restrict__ W2) {
    int i = blockIdx.x * blockDim.x + threadIdx.x;
    if (i < N_NODES) { g_count[i] = 0; g_fill[i] = 0; }
    if (i < N_NODES * IN_DIM / 4) {
        float4 v = ((const float4*)x)[i];
        __half2 h0 = __floats2half2_rn(v.x, v.y);
        __half2 h1 = __floats2half2_rn(v.z, v.w);
        uint2 u;
        u.x = *(const uint32_t*)&h0;
        u.y = *(const uint32_t*)&h1;
        ((uint2*)g_x16)[i] = u;
    }
    if (i < 256 * 128) {           // W1T[n][k] = W1[k][n]
        int n = i >> 7, k = i & 127;
        g_w1t[i] = __float2half_rn(W1[k * 256 + n]);
    }
    if (i < 256 * 256) {           // W2T[n][k] = W2[k][n]
        int n = i >> 8, k = i & 255;
        g_w2t[i] = __float2half_rn(W2[k * 256 + n]);
    }
}

__global__ void k_hist(const int* __restrict__ dst) {
    int e = blockIdx.x * blockDim.x + threadIdx.x;
    if (e < N_EDGES) atomicAdd(&g_count[dst[e]], 1);
}

// block-local exclusive scan + dinv; last block to finish scans the block sums
__global__ void k_scan1() {
    __shared__ int warpsums[32];
    __shared__ int s_last;
    int b = blockIdx.x;
    int i = b * SCAN_B + threadIdx.x;
    int v = (i < N_NODES) ? g_count[i] : 0;
    if (i < N_NODES) g_dinv[i] = rsqrtf((float)v + 1.0f);
    int lane = threadIdx.x & 31, w = threadIdx.x >> 5;
    int p = v;
#pragma unroll
    for (int off = 1; off < 32; off <<= 1) {
        int t = __shfl_up_sync(0xFFFFFFFFu, p, off);
        if (lane >= off) p += t;
    }
    if (lane == 31) warpsums[w] = p;
    __syncthreads();
    if (w == 0) {
        int s = warpsums[lane];
#pragma unroll
        for (int off = 1; off < 32; off <<= 1) {
            int t = __shfl_up_sync(0xFFFFFFFFu, s, off);
            if (lane >= off) s += t;
        }
        warpsums[lane] = s;
    }
    __syncthreads();
    int excl = p - v + (w > 0 ? warpsums[w - 1] : 0);
    if (i < N_NODES) g_rowptr[i] = excl;              // block-local exclusive
    if (threadIdx.x == SCAN_B - 1) g_bsum[b] = excl + v;

    __threadfence();
    __syncthreads();
    if (threadIdx.x == 0) {
        int t = atomicAdd(&g_ticket, 1);
        s_last = (t == NBLK - 1) ? 1 : 0;
    }
    __syncthreads();
    if (s_last) {
        if (threadIdx.x == 0) g_ticket = 0;           // reset for graph replay
        if (threadIdx.x < 32) {
            __threadfence();
            int l = threadIdx.x;
            int i0 = 2 * l, i1 = 2 * l + 1;
            int v0 = (i0 < NBLK) ? g_bsum[i0] : 0;
            int v1 = (i1 < NBLK) ? g_bsum[i1] : 0;
            int pr = v0 + v1;
            int s = pr;
#pragma unroll
            for (int off = 1; off < 32; off <<= 1) {
                int t = __shfl_up_sync(0xFFFFFFFFu, s, off);
                if (l >= off) s += t;
            }
            int e2 = s - pr;
            if (i0 < NBLK) g_boff[i0] = e2;
            if (i1 < NBLK) g_boff[i1] = e2 + v0;
            int total = __shfl_sync(0xFFFFFFFFu, s, 31);
            if (i0 == NBLK - 1) g_rowptr[N_NODES] = total - e2;
            if (i1 == NBLK - 1) g_rowptr[N_NODES] = total - (e2 + v0);
        }
    }
}

__global__ void k_sort(const int* __restrict__ src, const int* __restrict__ dst) {
    int e = blockIdx.x * blockDim.x + threadIdx.x;
    if (e >= N_EDGES) return;
    int d = dst[e];
    int pos = g_rowptr[d] + g_boff[d >> 10] + atomicAdd(&g_fill[d], 1);
    g_col[pos] = src[e];
}

#define H4_ACC(T, W)                                                   \
    {                                                                  \
        float2 f0 = __half22float2(*(const __half2*)&(T).x);           \
        float2 f1 = __half22float2(*(const __half2*)&(T).y);           \
        acc.x += (W) * f0.x; acc.y += (W) * f0.y;                      \
        acc.z += (W) * f1.x; acc.w += (W) * f1.y;                      \
    }

// 8-deep gather batch: 8 cols -> 8 dinv + 8 rows in flight (MLP 8)
#define AGG_BODY(RS)                                                          \
    int p = beg;                                                              \
    for (; p + 7 < end; p += 8) {                                             \
        int   sx[8];                                                          \
        float wx[8];                                                          \
        uint2 tx[8];                                                          \
        _Pragma("unroll")                                                     \
        for (int q = 0; q < 8; q++) sx[q] = g_col[p + q];                     \
        _Pragma("unroll")                                                     \
        for (int q = 0; q < 8; q++) wx[q] = g_dinv[sx[q]];                    \
        _Pragma("unroll")                                                     \
        for (int q = 0; q < 8; q++) tx[q] = base[(size_t)sx[q] * (RS)];       \
        _Pragma("unroll")                                                     \
        for (int q = 0; q < 8; q++) { H4_ACC(tx[q], wx[q]); }                 \
    }                                                                         \
    for (; p + 3 < end; p += 4) {                                             \
        int s0 = g_col[p],     s1 = g_col[p+1],                               \
            s2 = g_col[p+2],   s3 = g_col[p+3];                               \
        float w0 = g_dinv[s0], w1 = g_dinv[s1],                               \
              w2 = g_dinv[s2], w3 = g_dinv[s3];                               \
        uint2 t0 = base[(size_t)s0 * (RS)];                                   \
        uint2 t1 = base[(size_t)s1 * (RS)];                                   \
        uint2 t2 = base[(size_t)s2 * (RS)];                                   \
        uint2 t3 = base[(size_t)s3 * (RS)];                                   \
        H4_ACC(t0, w0); H4_ACC(t1, w1); H4_ACC(t2, w2); H4_ACC(t3, w3);       \
    }                                                                         \
    for (; p < end; p++) {                                                    \
        int s = g_col[p];                                                     \
        float wv = g_dinv[s];                                                 \
        uint2 t = base[(size_t)s * (RS)];                                     \
        H4_ACC(t, wv);                                                        \
    }

// ---------------- layer-1 aggregation (fp16 in/out, 128 cols, 1 warp/node) --
__global__ void k_agg1(const __half* __restrict__ in, __half* __restrict__ out) {
    int node = (blockIdx.x * blockDim.x + threadIdx.x) >> 5;
    int lane = threadIdx.x & 31;
    if (node >= N_NODES) return;
    int beg = g_rowptr[node]     + g_boff[node >> 10];
    int end = g_rowptr[node + 1] + g_boff[(node + 1) >> 10];
    float dn = g_dinv[node];
    const uint2* base = (const uint2*)in + lane;
    float4 acc = make_float4(0.f, 0.f, 0.f, 0.f);
    AGG_BODY(32)
    {
        uint2 t = base[(size_t)node * 32];
        float2 f0 = __half22float2(*(const __half2*)&t.x);
        float2 f1 = __half22float2(*(const __half2*)&t.y);
        __half2 h0 = __floats2half2_rn(dn * (acc.x + dn * f0.x),
                                       dn * (acc.y + dn * f0.y));
        __half2 h1 = __floats2half2_rn(dn * (acc.z + dn * f1.x),
                                       dn * (acc.w + dn * f1.y));
        uint2 u;
        u.x = *(const uint32_t*)&h0;
        u.y = *(const uint32_t*)&h1;
        ((uint2*)out)[(size_t)node * 32 + lane] = u;
    }
}

// ---------------- layer-2 aggregation (fp16 in/out, 256 cols, 2 warps/node) -
__global__ void k_agg2(const __half* __restrict__ in, __half* __restrict__ out) {
    int gw   = (blockIdx.x * blockDim.x + threadIdx.x) >> 5;
    int lane = threadIdx.x & 31;
    int node = gw >> 1;
    int half = gw & 1;
    if (node >= N_NODES) return;
    int beg = g_rowptr[node]     + g_boff[node >> 10];
    int end = g_rowptr[node + 1] + g_boff[(node + 1) >> 10];
    float dn = g_dinv[node];
    const uint2* base = (const uint2*)in + (size_t)half * 32 + lane;
    float4 acc = make_float4(0.f, 0.f, 0.f, 0.f);
    AGG_BODY(64)
    {
        uint2 t = base[(size_t)node * 64];
        float2 f0 = __half22float2(*(const __half2*)&t.x);
        float2 f1 = __half22float2(*(const __half2*)&t.y);
        __half2 h0 = __floats2half2_rn(dn * (acc.x + dn * f0.x),
                                       dn * (acc.y + dn * f0.y));
        __half2 h1 = __floats2half2_rn(dn * (acc.z + dn * f1.x),
                                       dn * (acc.w + dn * f1.y));
        uint2 u;
        u.x = *(const uint32_t*)&h0;
        u.y = *(const uint32_t*)&h1;
        ((uint2*)out)[(size_t)node * 64 + half * 32 + lane] = u;
    }
}
#undef AGG_BODY
#undef H4_ACC

// ---------------- fp16 MMA helper (m16n8k16, fp32 accum) ----------------
__device__ __forceinline__ void mma_f16(float c[4], uint32_t a0, uint32_t a1,
                                        uint32_t a2, uint32_t a3,
                                        uint32_t b0, uint32_t b1) {
    asm volatile(
        "mma.sync.aligned.m16n8k16.row.col.f32.f16.f16.f32 "
        "{%0,%1,%2,%3}, {%4,%5,%6,%7}, {%8,%9}, {%0,%1,%2,%3};"
        : "+f"(c[0]), "+f"(c[1]), "+f"(c[2]), "+f"(c[3])
        : "r"(a0), "r"(a1), "r"(a2), "r"(a3), "r"(b0), "r"(b1));
}

// ---------------- GEMM1 (fp16 TC): h1h = half(relu(xagg16 @ W1 + b1)) -------
#define PAD1 40   // halves per smem row (32 + 8); 80B stride

__global__ void __launch_bounds__(256, 2)
k_gemm1h(const __half* __restrict__ A, const __half* __restrict__ BT,
         const float* __restrict__ bias, __half* __restrict__ C, int M) {
    __shared__ __half As[2][128][PAD1];
    __shared__ __half Bs[2][128][PAD1];
    const int bm = blockIdx.x * 128;
    const int bn = blockIdx.y * 128;
    const int tid  = threadIdx.x;
    const int lane = tid & 31;
    const int warp = tid >> 5;
    const int wm = warp >> 2;
    const int wn = warp & 3;
    const int g   = lane >> 2;
    const int tig = lane & 3;
    const int a_r = tid >> 1;            // 0..127
    const int a_c = (tid & 1) * 16;      // 0 or 16 halves

    float c[4][4][4];
#pragma unroll
    for (int i = 0; i < 4; i++)
#pragma unroll
        for (int j = 0; j < 4; j++)
#pragma unroll
            for (int r = 0; r < 4; r++) c[i][j][r] = 0.f;

    const int m = bm + a_r;
    const bool mok = (m < M);
    uint4 ua0, ua1, ub0, ub1;

#define G1_LOAD(k0)                                                           \
    {                                                                         \
        ua0 = make_uint4(0, 0, 0, 0); ua1 = ua0;                              \
        if (mok) {                                                            \
            ua0 = *(const uint4*)(A + (size_t)m * 128 + (k0) + a_c);          \
            ua1 = *(const uint4*)(A + (size_t)m * 128 + (k0) + a_c + 8);      \
        }                                                                     \
        ub0 = *(const uint4*)(BT + (size_t)(bn + a_r) * 128 + (k0) + a_c);    \
        ub1 = *(const uint4*)(BT + (size_t)(bn + a_r) * 128 + (k0) + a_c + 8);\
    }
#define G1_STORE(buf)                                                         \
    {                                                                         \
        *(uint4*)&As[buf][a_r][a_c]     = ua0;                                \
        *(uint4*)&As[buf][a_r][a_c + 8] = ua1;                                \
        *(uint4*)&Bs[buf][a_r][a_c]     = ub0;                                \
        *(uint4*)&Bs[buf][a_r][a_c + 8] = ub1;                                \
    }

    G1_LOAD(0);
    G1_STORE(0);
    __syncthreads();
#pragma unroll
    for (int t = 0; t < 4; t++) {          // 128 / BK32
        if (t + 1 < 4) G1_LOAD((t + 1) * 32);
        const int buf = t & 1;
#pragma unroll
        for (int kk = 0; kk < 32; kk += 16) {
            uint32_t af[4][4], bf[4][2];
#pragma unroll
            for (int mt = 0; mt < 4; mt++) {
                int mb = wm * 64 + mt * 16;
                af[mt][0] = *(const uint32_t*)&As[buf][mb + g][kk + 2 * tig];
                af[mt][1] = *(const uint32_t*)&As[buf][mb + g + 8][kk + 2 * tig];
                af[mt][2] = *(const uint32_t*)&As[buf][mb + g][kk + 2 * tig + 8];
                af[mt][3] = *(const uint32_t*)&As[buf][mb + g + 8][kk + 2 * tig + 8];
            }
#pragma unroll
            for (int nt = 0; nt < 4; nt++) {
                int nb = wn * 32 + nt * 8;
                bf[nt][0] = *(const uint32_t*)&Bs[buf][nb + g][kk + 2 * tig];
                bf[nt][1] = *(const uint32_t*)&Bs[buf][nb + g][kk + 2 * tig + 8];
            }
#pragma unroll
            for (int mt = 0; mt < 4; mt++)
#pragma unroll
                for (int nt = 0; nt < 4; nt++)
                    mma_f16(c[mt][nt], af[mt][0], af[mt][1], af[mt][2],
                            af[mt][3], bf[nt][0], bf[nt][1]);
        }
        if (t + 1 < 4) G1_STORE((t + 1) & 1);
        __syncthreads();
    }

#pragma unroll
    for (int nt = 0; nt < 4; nt++) {
        int col = bn + wn * 32 + nt * 8 + tig * 2;
        float bb0 = bias[col], bb1 = bias[col + 1];
#pragma unroll
        for (int mt = 0; mt < 4; mt++) {
            int row0 = bm + wm * 64 + mt * 16 + g;
            int row1 = row0 + 8;
            if (row0 < M) {
                float vx = fmaxf(c[mt][nt][0] + bb0, 0.f);
                float vy = fmaxf(c[mt][nt][1] + bb1, 0.f);
                *(__half2*)(C + (size_t)row0 * 256 + col) =
                    __floats2half2_rn(vx, vy);
            }
            if (row1 < M) {
                float vx = fmaxf(c[mt][nt][2] + bb0, 0.f);
                float vy = fmaxf(c[mt][nt][3] + bb1, 0.f);
                *(__half2*)(C + (size_t)row1 * 256 + col) =
                    __floats2half2_rn(vx, vy);
            }
        }
    }
#undef G1_LOAD
#undef G1_STORE
}

// ---------------- GEMM2 (fp16 TC) + fused 256->2 projection ----------------
#define PAD2 24   // halves per smem row (16 + 8); 48B stride

__global__ void __launch_bounds__(256, 2)
k_gemm2fh(const __half* __restrict__ A, const __half* __restrict__ BT,
          const float* __restrict__ b2, const float* __restrict__ Wl,
          const float* __restrict__ bl, float* __restrict__ out, int M) {
    __shared__ __half As[2][64][PAD2];
    __shared__ __half Bs[2][256][PAD2];
    __shared__ float red[8][64][2];
    const int bm = blockIdx.x * 64;
    const int tid  = threadIdx.x;
    const int lane = tid & 31;
    const int wn   = tid >> 5;
    const int g    = lane >> 2;
    const int tig  = lane & 3;
    const int a_r  = tid >> 2;
    const int a_c  = (tid & 3) * 4;

    float c[4][4][4];
#pragma unroll
    for (int i = 0; i < 4; i++)
#pragma unroll
        for (int j = 0; j < 4; j++)
#pragma unroll
            for (int r = 0; r < 4; r++) c[i][j][r] = 0.f;

    const int m = bm + a_r;
    const bool mok = (m < M);
    uint2 ua;
    uint4 ub0, ub1;
    const int b_i0 = tid;
    const int b_i1 = tid + 256;
    const int b_r0 = b_i0 >> 1, b_c0 = (b_i0 & 1) * 8;
    const int b_r1 = b_i1 >> 1, b_c1 = (b_i1 & 1) * 8;

#define G2_LOAD(k0)                                                           \
    {                                                                         \
        ua = make_uint2(0, 0);                                                \
        if (mok) ua = *(const uint2*)(A + (size_t)m * 256 + (k0) + a_c);      \
        ub0 = *(const uint4*)(BT + (size_t)b_r0 * 256 + (k0) + b_c0);         \
        ub1 = *(const uint4*)(BT + (size_t)b_r1 * 256 + (k0) + b_c1);         \
    }
#define G2_STORE(buf)                                                         \
    {                                                                         \
        *(uint2*)&As[buf][a_r][a_c]   = ua;                                   \
        *(uint4*)&Bs[buf][b_r0][b_c0] = ub0;                                  \
        *(uint4*)&Bs[buf][b_r1][b_c1] = ub1;                                  \
    }

    G2_LOAD(0);
    G2_STORE(0);
    __syncthreads();
#pragma unroll
    for (int t = 0; t < 16; t++) {       // 256 / BK16
        if (t + 1 < 16) G2_LOAD((t + 1) * 16);
        const int buf = t & 1;
        uint32_t af[4][4], bf[4][2];
#pragma unroll
        for (int mt = 0; mt < 4; mt++) {
            int mb = mt * 16;
            af[mt][0] = *(const uint32_t*)&As[buf][mb + g][2 * tig];
            af[mt][1] = *(const uint32_t*)&As[buf][mb + g + 8][2 * tig];
            af[mt][2] = *(const uint32_t*)&As[buf][mb + g][2 * tig + 8];
            af[mt][3] = *(const uint32_t*)&As[buf][mb + g + 8][2 * tig + 8];
        }
#pragma unroll
        for (int nt = 0; nt < 4; nt++) {
            int nb = wn * 32 + nt * 8;
            bf[nt][0] = *(const uint32_t*)&Bs[buf][nb + g][2 * tig];
            bf[nt][1] = *(const uint32_t*)&Bs[buf][nb + g][2 * tig + 8];
        }
#pragma unroll
        for (int mt = 0; mt < 4; mt++)
#pragma unroll
            for (int nt = 0; nt < 4; nt++)
                mma_f16(c[mt][nt], af[mt][0], af[mt][1], af[mt][2], af[mt][3],
                        bf[nt][0], bf[nt][1]);
        if (t + 1 < 16) G2_STORE((t + 1) & 1);
        __syncthreads();
    }

    float wl0[8], wl1[8], bb[8];
#pragma unroll
    for (int nt = 0; nt < 4; nt++)
#pragma unroll
        for (int j = 0; j < 2; j++) {
            int col = wn * 32 + nt * 8 + tig * 2 + j;
            int idx = nt * 2 + j;
            bb[idx]  = b2[col];
            wl0[idx] = Wl[col * 2 + 0];
            wl1[idx] = Wl[col * 2 + 1];
        }
#pragma unroll
    for (int mt = 0; mt < 4; mt++) {
        float r0s0 = 0.f, r0s1 = 0.f, r1s0 = 0.f, r1s1 = 0.f;
#pragma unroll
        for (int nt = 0; nt < 4; nt++) {
            float v0 = fmaxf(c[mt][nt][0] + bb[nt * 2 + 0], 0.f);
            float v1 = fmaxf(c[mt][nt][1] + bb[nt * 2 + 1], 0.f);
            float v2 = fmaxf(c[mt][nt][2] + bb[nt * 2 + 0], 0.f);
            float v3 = fmaxf(c[mt][nt][3] + bb[nt * 2 + 1], 0.f);
            r0s0 += v0 * wl0[nt * 2] + v1 * wl0[nt * 2 + 1];
            r0s1 += v0 * wl1[nt * 2] + v1 * wl1[nt * 2 + 1];
            r1s0 += v2 * wl0[nt * 2] + v3 * wl0[nt * 2 + 1];
            r1s1 += v2 * wl1[nt * 2] + v3 * wl1[nt * 2 + 1];
        }
#pragma unroll
        for (int off = 1; off <= 2; off <<= 1) {
            r0s0 += __shfl_xor_sync(0xFFFFFFFFu, r0s0, off);
            r0s1 += __shfl_xor_sync(0xFFFFFFFFu, r0s1, off);
            r1s0 += __shfl_xor_sync(0xFFFFFFFFu, r1s0, off);
            r1s1 += __shfl_xor_sync(0xFFFFFFFFu, r1s1, off);
        }
        if (tig == 0) {
            red[wn][mt * 16 + g][0]     = r0s0;
            red[wn][mt * 16 + g][1]     = r0s1;
            red[wn][mt * 16 + 8 + g][0] = r1s0;
            red[wn][mt * 16 + 8 + g][1] = r1s1;
        }
    }
    __syncthreads();
    if (tid < 128) {
        int row = tid >> 1, d = tid & 1;
        float s = bl[d];
#pragma unroll
        for (int w = 0; w < 8; w++) s += red[w][row][d];
        int r = bm + row;
        if (r < M) out[(size_t)r * 2 + d] = s;
    }
#undef G2_LOAD
#undef G2_STORE
}

// ---------------- launch ----------------
extern "C" void kernel_launch(void* const* d_in, const int* in_sizes, int n_in,
                              void* d_out, int out_size) {
    const float* x   = (const float*)d_in[0];
    const int*   ei  = (const int*)d_in[1];
    const float* W1  = (const float*)d_in[2];
    const float* b1  = (const float*)d_in[3];
    const float* W2  = (const float*)d_in[4];
    const float* b2  = (const float*)d_in[5];
    const float* Wl  = (const float*)d_in[6];
    const float* bl  = (const float*)d_in[7];
    float* out = (float*)d_out;

    const int* src = ei;            // edge_index[0, :]
    const int* dst = ei + N_EDGES;  // edge_index[1, :]

    __half* x16;    cudaGetSymbolAddress((void**)&x16,    g_x16);
    __half* w1t;    cudaGetSymbolAddress((void**)&w1t,    g_w1t);
    __half* w2t;    cudaGetSymbolAddress((void**)&w2t,    g_w2t);
    __half* xagg16; cudaGetSymbolAddress((void**)&xagg16, g_xagg16);
    __half* h1h;    cudaGetSymbolAddress((void**)&h1h,    g_h1h);
    __half* h1agg;  cudaGetSymbolAddress((void**)&h1agg,  g_h1agg16);

    const int TB = 256;
    k_init<<<(N_NODES * IN_DIM / 4 + TB - 1) / TB, TB>>>(x, W1, W2);
    k_hist<<<(N_EDGES + TB - 1) / TB, TB>>>(dst);
    k_scan1<<<NBLK, SCAN_B>>>();
    k_sort<<<(N_EDGES + TB - 1) / TB, TB>>>(src, dst);

    // layer 1 (fp16 gather, 1 warp/node; fp16 MMA)
    {
        int blocks = (N_NODES * 32 + TB - 1) / TB;
        k_agg1<<<blocks, TB>>>(x16, xagg16);
    }
    {
        dim3 grid((N_NODES + 127) / 128, 2);
        k_gemm1h<<<grid, 256>>>(xagg16, w1t, b1, h1h, N_NODES);
    }
    // layer 2 + fused output projection (fp16 gather, 2 warps/node; fp16 MMA)
    {
        int blocks = (N_NODES * 2 * 32 + TB - 1) / TB;
        k_agg2<<<blocks, TB>>>(h1h, h1agg);
    }
    {
        int blocks = (N_NODES + 63) / 64;
        k_gemm2fh<<<blocks, 256>>>(h1agg, w2t, b2, Wl, bl, out, N_NODES);
    }
}